// round 5
// baseline (speedup 1.0000x reference)
#include <cuda_runtime.h>
#include <cstdint>

// A is [16384, 512] fp32 row-major.
// out = (||colsum||^2 - sum(A*A)) / (n*(n-1))
#define D      512
#define D4     128
#define GRID   256
#define TPB    512
#define ROWS_PER_BLOCK 64                 // 16384 / 256
#define STAGE_ROWS 8
#define NSTAGES 4                         // smem ring buffers
#define NITER   (ROWS_PER_BLOCK / STAGE_ROWS)     // 8
#define STAGE_BYTES (STAGE_ROWS * D * 4)          // 16384 B
#define DYN_SMEM (NSTAGES * STAGE_BYTES + 64)     // buffers + mbarriers
#define FAST_ROWS 16384

// Scratch (no allocs allowed). Fully overwritten each launch except g_count,
// which the last block resets.
__device__ float        g_part[GRID * D];
__device__ float        g_sqpart[GRID];
__device__ unsigned int g_count;

__device__ __forceinline__ uint32_t smem_u32(const void* p) {
    return (uint32_t)__cvta_generic_to_shared(p);
}

__device__ __forceinline__ void mbar_wait(uint32_t mb, uint32_t parity) {
    uint32_t done;
    asm volatile(
        "{\n\t.reg .pred p;\n\t"
        "mbarrier.try_wait.parity.acquire.cta.shared::cta.b64 p, [%1], %2;\n\t"
        "selp.b32 %0, 1, 0, p;\n\t}"
        : "=r"(done) : "r"(mb), "r"(parity) : "memory");
    if (!done) {
        asm volatile(
            "{\n\t.reg .pred P1;\n\t"
            "WAIT_LOOP_%=:\n\t"
            "mbarrier.try_wait.parity.acquire.cta.shared::cta.b64 P1, [%0], %1, 0x989680;\n\t"
            "@P1 bra.uni WAIT_DONE_%=;\n\t"
            "bra.uni WAIT_LOOP_%=;\n\t"
            "WAIT_DONE_%=:\n\t}"
            :: "r"(mb), "r"(parity) : "memory");
    }
}

__global__ void __launch_bounds__(TPB, 2)
ddc2_tma_kernel(const float* __restrict__ A, int n_rows, float* __restrict__ out) {
    extern __shared__ __align__(1024) char smem[];
    uint64_t* mbar = (uint64_t*)(smem + NSTAGES * STAGE_BYTES);

    const int t  = threadIdx.x;
    const int c4 = t & (D4 - 1);
    const int rs = t >> 7;           // row phase 0..3

    float ax = 0.f, ay = 0.f, az = 0.f, aw = 0.f;
    float sq = 0.f;

    if (n_rows == FAST_ROWS) {
        // ---- init mbarriers ----
        if (t == 0) {
            #pragma unroll
            for (int s = 0; s < NSTAGES; s++) {
                uint32_t mb = smem_u32(&mbar[s]);
                asm volatile("mbarrier.init.shared.b64 [%0], %1;"
                             :: "r"(mb), "r"(1) : "memory");
            }
            asm volatile("fence.proxy.async.shared::cta;" ::: "memory");
        }
        __syncthreads();

        const char* gbase =
            (const char*)(A + (size_t)blockIdx.x * ROWS_PER_BLOCK * D);

        // ---- prologue: fill all 4 stages ----
        if (t == 0) {
            #pragma unroll
            for (int s = 0; s < NSTAGES; s++) {
                uint32_t mb  = smem_u32(&mbar[s]);
                uint32_t dst = smem_u32(smem + s * STAGE_BYTES);
                asm volatile("mbarrier.arrive.expect_tx.shared.b64 _, [%0], %1;"
                             :: "r"(mb), "r"(STAGE_BYTES) : "memory");
                asm volatile(
                    "cp.async.bulk.shared::cta.global.mbarrier::complete_tx::bytes "
                    "[%0], [%1], %2, [%3];"
                    :: "r"(dst), "l"(gbase + (size_t)s * STAGE_BYTES),
                       "r"(STAGE_BYTES), "r"(mb) : "memory");
            }
        }

        // ---- mainloop: 8 stages through 4 buffers ----
        for (int s = 0; s < NITER; s++) {
            const int b      = s & (NSTAGES - 1);
            const int parity = s >> 2;           // 0 first pass, 1 second
            mbar_wait(smem_u32(&mbar[b]), parity);

            const float4* s4 = (const float4*)(smem + b * STAGE_BYTES);
            float4 v0 = s4[(rs * 2 + 0) * D4 + c4];
            float4 v1 = s4[(rs * 2 + 1) * D4 + c4];

            ax += v0.x + v1.x; ay += v0.y + v1.y;
            az += v0.z + v1.z; aw += v0.w + v1.w;
            sq = fmaf(v0.x, v0.x, sq); sq = fmaf(v0.y, v0.y, sq);
            sq = fmaf(v0.z, v0.z, sq); sq = fmaf(v0.w, v0.w, sq);
            sq = fmaf(v1.x, v1.x, sq); sq = fmaf(v1.y, v1.y, sq);
            sq = fmaf(v1.z, v1.z, sq); sq = fmaf(v1.w, v1.w, sq);

            __syncthreads();   // everyone done reading buffer b
            if (s + NSTAGES < NITER && t == 0) {
                uint32_t mb  = smem_u32(&mbar[b]);
                uint32_t dst = smem_u32(smem + b * STAGE_BYTES);
                asm volatile("mbarrier.arrive.expect_tx.shared.b64 _, [%0], %1;"
                             :: "r"(mb), "r"(STAGE_BYTES) : "memory");
                asm volatile(
                    "cp.async.bulk.shared::cta.global.mbarrier::complete_tx::bytes "
                    "[%0], [%1], %2, [%3];"
                    :: "r"(dst), "l"(gbase + (size_t)(s + NSTAGES) * STAGE_BYTES),
                       "r"(STAGE_BYTES), "r"(mb) : "memory");
            }
        }
    } else {
        // Generic fallback (unused for this fixed shape).
        const float4* __restrict__ A4 = reinterpret_cast<const float4*>(A);
        for (int row = blockIdx.x * 4 + rs; row < n_rows; row += GRID * 4) {
            float4 v = A4[(size_t)row * D4 + c4];
            ax += v.x; ay += v.y; az += v.z; aw += v.w;
            sq = fmaf(v.x, v.x, sq); sq = fmaf(v.y, v.y, sq);
            sq = fmaf(v.z, v.z, sq); sq = fmaf(v.w, v.w, sq);
        }
    }

    // ---- combine the 4 row-phases via (static) smem ----
    __shared__ float4 sc[4][D4];
    sc[rs][c4] = make_float4(ax, ay, az, aw);

    #pragma unroll
    for (int off = 16; off > 0; off >>= 1)
        sq += __shfl_xor_sync(0xFFFFFFFFu, sq, off);

    __shared__ float swarp[TPB / 32];
    if ((t & 31) == 0) swarp[t >> 5] = sq;
    __syncthreads();

    // ---- non-atomic partial writes: private row per block ----
    float4* __restrict__ P4 = reinterpret_cast<float4*>(g_part);
    if (t < D4) {
        float4 s0 = sc[0][t], s1 = sc[1][t], s2 = sc[2][t], s3 = sc[3][t];
        float4 r;
        r.x = (s0.x + s1.x) + (s2.x + s3.x);
        r.y = (s0.y + s1.y) + (s2.y + s3.y);
        r.z = (s0.z + s1.z) + (s2.z + s3.z);
        r.w = (s0.w + s1.w) + (s2.w + s3.w);
        P4[blockIdx.x * D4 + t] = r;
    }
    if (t < TPB / 32) {
        float w = swarp[t];
        #pragma unroll
        for (int off = 8; off > 0; off >>= 1)
            w += __shfl_xor_sync(0xFFFFu, w, off);
        if (t == 0) g_sqpart[blockIdx.x] = w;
    }

    // ---- last-block-finishes (only atomic: the counter) ----
    __syncthreads();
    __shared__ int is_last;
    if (t == 0) {
        __threadfence();
        unsigned prev = atomicAdd(&g_count, 1u);
        is_last = (prev == gridDim.x - 1u);
    }
    __syncthreads();

    if (is_last) {
        // Reduce the 256x512 partial matrix (L2-resident).
        float4 acc = make_float4(0.f, 0.f, 0.f, 0.f);
        #pragma unroll 8
        for (int k = 0; k < GRID / 4; k++) {
            float4 v = P4[(size_t)(rs + 4 * k) * D4 + c4];
            acc.x += v.x; acc.y += v.y; acc.z += v.z; acc.w += v.w;
        }
        sc[rs][c4] = acc;
        float q = (t < GRID) ? g_sqpart[t] : 0.f;
        __syncthreads();

        float p = 0.f;
        if (t < D4) {
            float4 s0 = sc[0][t], s1 = sc[1][t], s2 = sc[2][t], s3 = sc[3][t];
            float cx = (s0.x + s1.x) + (s2.x + s3.x);
            float cy = (s0.y + s1.y) + (s2.y + s3.y);
            float cz = (s0.z + s1.z) + (s2.z + s3.z);
            float cw = (s0.w + s1.w) + (s2.w + s3.w);
            p = cx * cx + cy * cy + cz * cz + cw * cw;
        }

        float r = p - q;
        #pragma unroll
        for (int off = 16; off > 0; off >>= 1)
            r += __shfl_xor_sync(0xFFFFFFFFu, r, off);

        __shared__ float fwarp[TPB / 32];
        if ((t & 31) == 0) fwarp[t >> 5] = r;
        __syncthreads();

        if (t == 0) {
            float tot = 0.f;
            #pragma unroll
            for (int w = 0; w < TPB / 32; w++) tot += fwarp[w];
            double denom = (double)n_rows * (double)(n_rows - 1);
            out[0] = (float)((double)tot / denom);
            g_count = 0u;   // reset for next graph replay
        }
    }
}

extern "C" void kernel_launch(void* const* d_in, const int* in_sizes, int n_in,
                              void* d_out, int out_size) {
    const float* A = (const float*)d_in[0];
    const int n_rows = in_sizes[0] / D;   // 16384

    // >48KB dynamic smem needs the opt-in attribute (idempotent, not a
    // stream op, not an allocation).
    cudaFuncSetAttribute(ddc2_tma_kernel,
                         cudaFuncAttributeMaxDynamicSharedMemorySize, DYN_SMEM);
    ddc2_tma_kernel<<<GRID, TPB, DYN_SMEM>>>(A, n_rows, (float*)d_out);
}

// round 6
// speedup vs baseline: 1.1628x; 1.1628x over previous
#include <cuda_runtime.h>
#include <cstdint>

// A is [16384, 512] fp32 row-major.
// out = (||colsum||^2 - sum(A*A)) / (n*(n-1))
#define D      512
#define D4     128
#define GRID   128
#define TPB    512
#define ROWS_PER_BLOCK 128           // 16384 / 128
#define FAST_ROWS 16384
#define NGROUPS 16                   // 8 blocks per group

// Scratch (no allocations allowed). All data arrays fully overwritten each
// launch; counters reset by the final block before kernel end.
__device__ float        g_part[GRID * D];     // per-block colsum partials
__device__ float        g_sqpart[GRID];       // per-block sumsq partials
__device__ float        g_gpart[NGROUPS * D]; // per-group colsum partials
__device__ float        g_gsq[NGROUPS];       // per-group sumsq partials
__device__ unsigned int g_gcount[NGROUPS];
__device__ unsigned int g_fcount;

__global__ void __launch_bounds__(TPB, 1)
ddc2_kernel(const float* __restrict__ A, int n_rows, float* __restrict__ out) {
    const int t  = threadIdx.x;
    const int c4 = t & (D4 - 1);     // float4 column chunk owned by this thread
    const int rs = t >> 7;           // row phase 0..3

    const float4* __restrict__ A4 = reinterpret_cast<const float4*>(A);

    float ax = 0.f, ay = 0.f, az = 0.f, aw = 0.f;
    float sq = 0.f;

    if (n_rows == FAST_ROWS) {
        // Block owns 128 consecutive rows; phase rs owns 32 of them.
        // Two front-batches of 16 independent LDG.128 (reg budget 128 ->
        // ptxas can keep the whole batch in flight).
        const int r0 = blockIdx.x * ROWS_PER_BLOCK + rs * 32;
        const size_t base = (size_t)r0 * D4 + c4;
        #pragma unroll
        for (int half = 0; half < 2; half++) {
            float4 v[16];
            #pragma unroll
            for (int i = 0; i < 16; i++)
                v[i] = A4[base + (size_t)(half * 16 + i) * D4];
            #pragma unroll
            for (int i = 0; i < 16; i++) {
                ax += v[i].x; ay += v[i].y; az += v[i].z; aw += v[i].w;
                sq = fmaf(v[i].x, v[i].x, sq);
                sq = fmaf(v[i].y, v[i].y, sq);
                sq = fmaf(v[i].z, v[i].z, sq);
                sq = fmaf(v[i].w, v[i].w, sq);
            }
        }
    } else {
        // Generic fallback (unused for this fixed shape).
        for (int row = blockIdx.x * 4 + rs; row < n_rows; row += GRID * 4) {
            float4 v = A4[(size_t)row * D4 + c4];
            ax += v.x; ay += v.y; az += v.z; aw += v.w;
            sq = fmaf(v.x, v.x, sq); sq = fmaf(v.y, v.y, sq);
            sq = fmaf(v.z, v.z, sq); sq = fmaf(v.w, v.w, sq);
        }
    }

    // ---- combine the 4 row-phases via smem ----
    __shared__ float4 sc[4][D4];
    sc[rs][c4] = make_float4(ax, ay, az, aw);

    #pragma unroll
    for (int off = 16; off > 0; off >>= 1)
        sq += __shfl_xor_sync(0xFFFFFFFFu, sq, off);

    __shared__ float swarp[TPB / 32];
    if ((t & 31) == 0) swarp[t >> 5] = sq;
    __syncthreads();

    // ---- non-atomic partial write: private row per block ----
    float4* __restrict__ P4 = reinterpret_cast<float4*>(g_part);
    if (t < D4) {
        float4 s0 = sc[0][t], s1 = sc[1][t], s2 = sc[2][t], s3 = sc[3][t];
        float4 r;
        r.x = (s0.x + s1.x) + (s2.x + s3.x);
        r.y = (s0.y + s1.y) + (s2.y + s3.y);
        r.z = (s0.z + s1.z) + (s2.z + s3.z);
        r.w = (s0.w + s1.w) + (s2.w + s3.w);
        P4[blockIdx.x * D4 + t] = r;
    }
    if (t < TPB / 32) {
        float w = swarp[t];
        #pragma unroll
        for (int off = 8; off > 0; off >>= 1)
            w += __shfl_xor_sync(0xFFFFu, w, off);
        if (t == 0) g_sqpart[blockIdx.x] = w;
    }

    // ---- level 1: last block of each 8-block group folds the group ----
    const int grp = blockIdx.x >> 3;
    __syncthreads();
    __shared__ int sh_glast;
    if (t == 0) {
        __threadfence();
        unsigned prev = atomicAdd(&g_gcount[grp], 1u);
        sh_glast = (prev == 7u);
    }
    __syncthreads();
    if (!sh_glast) return;

    {
        // Thread t owns column t: fold 8 rows (coalesced scalar loads).
        float s = 0.f;
        #pragma unroll
        for (int j = 0; j < 8; j++)
            s += g_part[(size_t)(grp * 8 + j) * D + t];
        g_gpart[(size_t)grp * D + t] = s;
        if (t == 0) {
            float qs = 0.f;
            #pragma unroll
            for (int j = 0; j < 8; j++) qs += g_sqpart[grp * 8 + j];
            g_gsq[grp] = qs;
        }
    }

    // ---- level 2: last group folds 16 group rows and finalizes ----
    __syncthreads();
    __shared__ int sh_flast;
    if (t == 0) {
        __threadfence();
        unsigned prev = atomicAdd(&g_fcount, 1u);
        sh_flast = (prev == NGROUPS - 1u);
    }
    __syncthreads();
    if (!sh_flast) return;

    {
        float c = 0.f;
        #pragma unroll
        for (int g = 0; g < NGROUPS; g++)
            c += g_gpart[(size_t)g * D + t];

        float p = c * c;                               // ||colsum||^2 partial
        float q = (t < NGROUPS) ? g_gsq[t] : 0.f;      // sumsq partials
        float r = p - q;

        #pragma unroll
        for (int off = 16; off > 0; off >>= 1)
            r += __shfl_xor_sync(0xFFFFFFFFu, r, off);

        __shared__ float fwarp[TPB / 32];
        if ((t & 31) == 0) fwarp[t >> 5] = r;
        __syncthreads();

        // reset counters for the next graph replay
        if (t < NGROUPS) g_gcount[t] = 0u;

        if (t == 0) {
            float tot = 0.f;
            #pragma unroll
            for (int w = 0; w < TPB / 32; w++) tot += fwarp[w];
            double denom = (double)n_rows * (double)(n_rows - 1);
            out[0] = (float)((double)tot / denom);
            g_fcount = 0u;
        }
    }
}

extern "C" void kernel_launch(void* const* d_in, const int* in_sizes, int n_in,
                              void* d_out, int out_size) {
    const float* A = (const float*)d_in[0];
    const int n_rows = in_sizes[0] / D;   // 16384
    ddc2_kernel<<<GRID, TPB>>>(A, n_rows, (float*)d_out);
}

// round 7
// speedup vs baseline: 1.1869x; 1.0208x over previous
#include <cuda_runtime.h>
#include <cstdint>

// A is [16384, 512] fp32 row-major.
// out = (||colsum||^2 - sum(A*A)) / (n*(n-1))
#define D      512
#define D4     128
#define GRID   148                   // one CTA per SM, full chip
#define TPB    512
#define NGROUPS 37                   // 148 / 4 blocks per group

// Scratch (no allocations allowed). Data arrays fully overwritten each
// launch; counters reset by the final block.
__device__ float        g_part[GRID * D];      // per-block colsum partials
__device__ float        g_sqpart[GRID];        // per-block sumsq partials
__device__ float        g_gpart[NGROUPS * D];  // per-group colsum partials
__device__ float        g_gsq[NGROUPS];        // per-group sumsq partials
__device__ unsigned int g_gcount[NGROUPS];
__device__ unsigned int g_fcount;

__global__ void __launch_bounds__(TPB, 1)
ddc2_kernel(const float* __restrict__ A, int n_rows, float* __restrict__ out) {
    const int t  = threadIdx.x;
    const int c4 = t & (D4 - 1);     // float4 column chunk (invariant: stride % 128 == 0)
    const int rs = t >> 7;           // phase 0..3 for the smem combine

    const float4* __restrict__ A4 = reinterpret_cast<const float4*>(A);
    const size_t N4     = (size_t)n_rows * D4;       // total float4 elements
    const size_t stride = (size_t)GRID * TPB;        // 75776, multiple of 128
    size_t i = (size_t)blockIdx.x * TPB + t;

    float ax = 0.f, ay = 0.f, az = 0.f, aw = 0.f;
    float sq = 0.f;

    // Main: batches of 8 independent LDG.128 (MLP=8, 32 payload regs).
    if (N4 >= 7 * stride) {
        const size_t limit = N4 - 7 * stride;
        while (i < limit) {
            float4 v[8];
            #pragma unroll
            for (int j = 0; j < 8; j++)
                v[j] = A4[i + (size_t)j * stride];
            #pragma unroll
            for (int j = 0; j < 8; j++) {
                ax += v[j].x; ay += v[j].y; az += v[j].z; aw += v[j].w;
                sq = fmaf(v[j].x, v[j].x, sq);
                sq = fmaf(v[j].y, v[j].y, sq);
                sq = fmaf(v[j].z, v[j].z, sq);
                sq = fmaf(v[j].w, v[j].w, sq);
            }
            i += 8 * stride;
        }
    }
    // Remainder (3-4 iterations for the 16384x512 shape).
    for (; i < N4; i += stride) {
        float4 v = A4[i];
        ax += v.x; ay += v.y; az += v.z; aw += v.w;
        sq = fmaf(v.x, v.x, sq); sq = fmaf(v.y, v.y, sq);
        sq = fmaf(v.z, v.z, sq); sq = fmaf(v.w, v.w, sq);
    }

    // ---- combine the 4 phases via smem ----
    __shared__ float4 sc[4][D4];
    sc[rs][c4] = make_float4(ax, ay, az, aw);

    #pragma unroll
    for (int off = 16; off > 0; off >>= 1)
        sq += __shfl_xor_sync(0xFFFFFFFFu, sq, off);

    __shared__ float swarp[TPB / 32];
    if ((t & 31) == 0) swarp[t >> 5] = sq;
    __syncthreads();

    // ---- non-atomic partial write: private row per block ----
    float4* __restrict__ P4 = reinterpret_cast<float4*>(g_part);
    if (t < D4) {
        float4 s0 = sc[0][t], s1 = sc[1][t], s2 = sc[2][t], s3 = sc[3][t];
        float4 r;
        r.x = (s0.x + s1.x) + (s2.x + s3.x);
        r.y = (s0.y + s1.y) + (s2.y + s3.y);
        r.z = (s0.z + s1.z) + (s2.z + s3.z);
        r.w = (s0.w + s1.w) + (s2.w + s3.w);
        P4[blockIdx.x * D4 + t] = r;
    }
    if (t < TPB / 32) {
        float w = swarp[t];
        #pragma unroll
        for (int off = 8; off > 0; off >>= 1)
            w += __shfl_xor_sync(0xFFFFu, w, off);
        if (t == 0) g_sqpart[blockIdx.x] = w;
    }

    // ---- level 1: last block of each 4-block group folds the group ----
    const int grp = blockIdx.x >> 2;            // 148 = 37 groups of 4
    __syncthreads();
    __shared__ int sh_glast;
    if (t == 0) {
        __threadfence();
        unsigned prev = atomicAdd(&g_gcount[grp], 1u);
        sh_glast = (prev == 3u);
    }
    __syncthreads();
    if (!sh_glast) return;

    {
        float s = 0.f;
        #pragma unroll
        for (int j = 0; j < 4; j++)
            s += g_part[(size_t)(grp * 4 + j) * D + t];
        g_gpart[(size_t)grp * D + t] = s;
        if (t == 0) {
            float qs = 0.f;
            #pragma unroll
            for (int j = 0; j < 4; j++) qs += g_sqpart[grp * 4 + j];
            g_gsq[grp] = qs;
        }
    }

    // ---- level 2: last group folds 37 group rows and finalizes ----
    __syncthreads();
    __shared__ int sh_flast;
    if (t == 0) {
        __threadfence();
        unsigned prev = atomicAdd(&g_fcount, 1u);
        sh_flast = (prev == NGROUPS - 1u);
    }
    __syncthreads();
    if (!sh_flast) return;

    {
        float c = 0.f;
        #pragma unroll
        for (int g = 0; g < NGROUPS; g++)
            c += g_gpart[(size_t)g * D + t];

        float p = c * c;                               // ||colsum||^2 partial
        float q = (t < NGROUPS) ? g_gsq[t] : 0.f;      // sumsq partials
        float r = p - q;

        #pragma unroll
        for (int off = 16; off > 0; off >>= 1)
            r += __shfl_xor_sync(0xFFFFFFFFu, r, off);

        __shared__ float fwarp[TPB / 32];
        if ((t & 31) == 0) fwarp[t >> 5] = r;
        __syncthreads();

        // reset counters for the next graph replay
        if (t < NGROUPS) g_gcount[t] = 0u;

        if (t == 0) {
            float tot = 0.f;
            #pragma unroll
            for (int w = 0; w < TPB / 32; w++) tot += fwarp[w];
            double denom = (double)n_rows * (double)(n_rows - 1);
            out[0] = (float)((double)tot / denom);
            g_fcount = 0u;
        }
    }
}

extern "C" void kernel_launch(void* const* d_in, const int* in_sizes, int n_in,
                              void* d_out, int out_size) {
    const float* A = (const float*)d_in[0];
    const int n_rows = in_sizes[0] / D;   // 16384
    ddc2_kernel<<<GRID, TPB>>>(A, n_rows, (float*)d_out);
}